// round 16
// baseline (speedup 1.0000x reference)
#include <cuda_runtime.h>
#include <math.h>

#define N_NODES  100000
#define N_EDGES  1200000
#define N_GRAPHS 256
#define HID      64
#define SCAN_NB  391   // ceil(N_NODES / 256)

// ---------------- scratch (device globals: allocation-free) ----------------
__device__ __align__(16) float g_h1[N_NODES * HID];
__device__ __align__(16) float g_h2[N_NODES * HID];
__device__ __align__(16) float g_agg1[N_NODES * 3];
__device__ __align__(16) float g_agg2[N_NODES * HID];
__device__ __align__(16) float g_agg3[N_NODES * HID];
__device__ float g_stats1[128];
__device__ float g_stats2[128];
__device__ float g_sc1[64], g_sh1[64];
__device__ float g_sc2[64], g_sh2[64];
__device__ __align__(16) float g_pool[N_GRAPHS * HID];
// CSR-by-destination
__device__ int g_deg[N_NODES];
__device__ int g_off[N_NODES + 1];
__device__ int g_cur[N_NODES];
__device__ int g_csr[N_EDGES];
__device__ int g_bsums[512];

// ---------------- helpers ----------------
__device__ __forceinline__ void red_add_v4(float* p, float4 v) {
    asm volatile("red.global.add.v4.f32 [%0], {%1,%2,%3,%4};"
                 :: "l"(p), "f"(v.x), "f"(v.y), "f"(v.z), "f"(v.w)
                 : "memory");
}
// packed fp32x2 FMA (Blackwell): d = a * b + d, on two fp32 lanes at once
__device__ __forceinline__ unsigned long long pack2f(float lo, float hi) {
    unsigned long long r;
    asm("mov.b64 %0, {%1, %2};" : "=l"(r) : "f"(lo), "f"(hi));
    return r;
}
__device__ __forceinline__ void unpack2f(unsigned long long v, float& lo, float& hi) {
    asm("mov.b64 {%0, %1}, %2;" : "=f"(lo), "=f"(hi) : "l"(v));
}
__device__ __forceinline__ void fma2(unsigned long long& d,
                                     unsigned long long a, unsigned long long b) {
    asm("fma.rn.f32x2 %0, %1, %2, %3;" : "=l"(d) : "l"(a), "l"(b), "l"(d));
}

// ---------------- zero small scratch (incl. agg1 for atomic scatter) -------
__global__ void zero_small() {
    int i = blockIdx.x * blockDim.x + threadIdx.x;
    if (i < N_NODES) {
        g_deg[i] = 0;
        g_agg1[i * 3 + 0] = 0.f;
        g_agg1[i * 3 + 1] = 0.f;
        g_agg1[i * 3 + 2] = 0.f;
    }
    if (i < 128) { g_stats1[i] = 0.f; g_stats2[i] = 0.f; }
    if (i < N_GRAPHS * 16)
        reinterpret_cast<float4*>(g_pool)[i] = make_float4(0.f, 0.f, 0.f, 0.f);
}

// ---------------- merged edge pass: degree hist + 3-ch scatter -------------
__global__ void k_edge1(const int* __restrict__ ei, const float* __restrict__ x) {
    int e = blockIdx.x * blockDim.x + threadIdx.x;
    if (e >= N_EDGES) return;
    int s = ei[e];
    int d = ei[N_EDGES + e];
    atomicAdd(&g_deg[d], 1);
    const float* xr = x + 3 * (size_t)s;
    float* ar = g_agg1 + 3 * (size_t)d;
    atomicAdd(ar + 0, xr[0]);
    atomicAdd(ar + 1, xr[1]);
    atomicAdd(ar + 2, xr[2]);
}

// ---------------- CSR build: scan -> scatter ----------------
__global__ void k_scanA() {
    __shared__ int sh[256];
    int t = threadIdx.x;
    int i = blockIdx.x * 256 + t;
    sh[t] = (i < N_NODES) ? g_deg[i] : 0;
    __syncthreads();
    for (int s = 128; s > 0; s >>= 1) {
        if (t < s) sh[t] += sh[t + s];
        __syncthreads();
    }
    if (t == 0) g_bsums[blockIdx.x] = sh[0];
}

__global__ void k_scanB() {
    __shared__ int a[512], b[512];
    int t = threadIdx.x;
    int v = (t < SCAN_NB) ? g_bsums[t] : 0;
    a[t] = v;
    __syncthreads();
    int* src = a; int* dst = b;
    for (int off = 1; off < 512; off <<= 1) {
        dst[t] = src[t] + ((t >= off) ? src[t - off] : 0);
        __syncthreads();
        int* tmp = src; src = dst; dst = tmp;
    }
    if (t < SCAN_NB) g_bsums[t] = src[t] - v;   // exclusive
}

__global__ void k_scanC() {
    __shared__ int a[256], b[256];
    int t = threadIdx.x;
    int i = blockIdx.x * 256 + t;
    int v = (i < N_NODES) ? g_deg[i] : 0;
    a[t] = v;
    __syncthreads();
    int* src = a; int* dst = b;
    for (int off = 1; off < 256; off <<= 1) {
        dst[t] = src[t] + ((t >= off) ? src[t - off] : 0);
        __syncthreads();
        int* tmp = src; src = dst; dst = tmp;
    }
    int excl = src[t] - v + g_bsums[blockIdx.x];
    if (i < N_NODES) { g_off[i] = excl; g_cur[i] = excl; }
    if (i == 0) g_off[N_NODES] = N_EDGES;
}

__global__ void k_build(const int* __restrict__ ei) {
    int e = blockIdx.x * blockDim.x + threadIdx.x;
    if (e >= N_EDGES) return;
    int d = ei[N_EDGES + e];
    int s = ei[e];
    int p = atomicAdd(&g_cur[d], 1);
    g_csr[p] = s;
}

// ---------------- 64-ch aggregate: RAW sums (BN applied later in MLP) ------
// out[n] = e1·h_n + Σ_{s→n} h_s        (warp-per-node, divergence-free)
template <int L>
__global__ __launch_bounds__(256) void k_agg64(const float* __restrict__ epsp) {
    const float* __restrict__ h = (L == 2) ? g_h1  : g_h2;
    float* __restrict__ agg     = (L == 2) ? g_agg2 : g_agg3;

    int n = (blockIdx.x * 256 + threadIdx.x) >> 5;   // one warp per node
    if (n >= N_NODES) return;
    int lane = threadIdx.x & 31;
    int c = lane * 2;
    int st = g_off[n], en = g_off[n + 1];
    float e1 = 1.0f + *epsp;

    float2 a = *reinterpret_cast<const float2*>(h + (size_t)n * HID + c);
    a.x *= e1; a.y *= e1;
    for (int e = st; e < en; e++) {
        int s = __ldg(&g_csr[e]);
        float2 v = *reinterpret_cast<const float2*>(h + (size_t)s * HID + c);
        a.x += v.x; a.y += v.y;
    }
    *reinterpret_cast<float2*>(agg + (size_t)n * HID + c) = a;
}

// ---------------- layer-1 node MLP: 3 -> 64 -> 64, outer relu ----------------
__global__ __launch_bounds__(128) void node_mlp1(
    const float* __restrict__ x, const float* __restrict__ epsp,
    const float* __restrict__ wa, const float* __restrict__ ba,
    const float* __restrict__ wb, const float* __restrict__ bb)
{
    __shared__ __align__(16) float swa[3 * 64];
    __shared__ __align__(16) float swb[64 * 64];
    __shared__ __align__(16) float sba[64];
    __shared__ __align__(16) float sbb[64];
    for (int i = threadIdx.x; i < 64 * 64; i += 128) swb[i] = wb[i];
    for (int i = threadIdx.x; i < 192; i += 128) swa[i] = wa[i];
    if (threadIdx.x < 64) { sba[threadIdx.x] = ba[threadIdx.x]; sbb[threadIdx.x] = bb[threadIdx.x]; }
    __syncthreads();

    int n = blockIdx.x * 128 + threadIdx.x;
    if (n >= N_NODES) return;
    float e1 = 1.0f + *epsp;
    float v0 = fmaf(e1, x[n * 3 + 0], g_agg1[n * 3 + 0]);
    float v1 = fmaf(e1, x[n * 3 + 1], g_agg1[n * 3 + 1]);
    float v2 = fmaf(e1, x[n * 3 + 2], g_agg1[n * 3 + 2]);

    float t[64];
#pragma unroll
    for (int j = 0; j < 64; j++)
        t[j] = fmaxf(fmaf(v2, swa[128 + j], fmaf(v1, swa[64 + j], fmaf(v0, swa[j], sba[j]))), 0.0f);

    // second GEMM with packed f32x2 FMA, chunks of 16 outputs
    float* orow = g_h1 + (size_t)n * HID;
    const unsigned long long* sbb2 = reinterpret_cast<const unsigned long long*>(sbb);
#pragma unroll
    for (int j0 = 0; j0 < 64; j0 += 16) {
        unsigned long long o[8];
#pragma unroll
        for (int u = 0; u < 8; u++) o[u] = sbb2[j0 / 2 + u];
#pragma unroll 8
        for (int k = 0; k < 64; k++) {
            unsigned long long vv = pack2f(t[k], t[k]);
            const ulonglong2* wr = reinterpret_cast<const ulonglong2*>(&swb[k * 64 + j0]);
#pragma unroll
            for (int j = 0; j < 4; j++) {
                ulonglong2 w = wr[j];
                fma2(o[2 * j], vv, w.x);
                fma2(o[2 * j + 1], vv, w.y);
            }
        }
        float r[16];
#pragma unroll
        for (int u = 0; u < 8; u++) {
            float lo, hi; unpack2f(o[u], lo, hi);
            r[2 * u] = fmaxf(lo, 0.f); r[2 * u + 1] = fmaxf(hi, 0.f);
        }
#pragma unroll
        for (int j = 0; j < 16; j += 4)
            *reinterpret_cast<float4*>(orow + j0 + j) =
                make_float4(r[j], r[j + 1], r[j + 2], r[j + 3]);
    }
}

// ---------------- layer-2/3 node MLP: BN-fold at input + 64->64->64 --------
// v = sc ⊙ a_raw + (e1 + deg)·sh ; packed f32x2 FMA throughout
template <int L>
__global__ __launch_bounds__(128) void node_mlp64(
    const float* __restrict__ epsp,
    const float* __restrict__ wa, const float* __restrict__ ba,
    const float* __restrict__ wb, const float* __restrict__ bb,
    const int* __restrict__ batch)
{
    const float* __restrict__ agg = (L == 2) ? g_agg2 : g_agg3;
    const float* __restrict__ sc  = (L == 2) ? g_sc1 : g_sc2;
    const float* __restrict__ sh  = (L == 2) ? g_sh1 : g_sh2;

    __shared__ __align__(16) float swa[4096];
    __shared__ __align__(16) float swb[4096];
    __shared__ __align__(16) float sba[64];
    __shared__ __align__(16) float sbb[64];
    __shared__ __align__(16) float ssc[64];
    __shared__ __align__(16) float ssh[64];
    for (int i = threadIdx.x; i < 4096; i += 128) { swa[i] = wa[i]; swb[i] = wb[i]; }
    if (threadIdx.x < 64) {
        int j = threadIdx.x;
        sba[j] = ba[j]; sbb[j] = bb[j]; ssc[j] = sc[j]; ssh[j] = sh[j];
    }
    __syncthreads();

    int n = blockIdx.x * 128 + threadIdx.x;
    if (n >= N_NODES) return;
    float e1 = 1.0f + *epsp;
    float cnt = e1 + (float)(g_off[n + 1] - g_off[n]);
    const float4* ar4 = reinterpret_cast<const float4*>(agg + (size_t)n * HID);

    // ---- GEMM 1: all 64 outputs as 32 packed accumulators ----
    unsigned long long acc[32];
    const unsigned long long* sba2 = reinterpret_cast<const unsigned long long*>(sba);
#pragma unroll
    for (int j = 0; j < 32; j++) acc[j] = sba2[j];
#pragma unroll 4
    for (int k4 = 0; k4 < 16; k4++) {
        float4 av = ar4[k4];
        float4 scv = *reinterpret_cast<const float4*>(&ssc[k4 * 4]);
        float4 shv = *reinterpret_cast<const float4*>(&ssh[k4 * 4]);
        float vv4[4];
        vv4[0] = fmaf(av.x, scv.x, cnt * shv.x);
        vv4[1] = fmaf(av.y, scv.y, cnt * shv.y);
        vv4[2] = fmaf(av.z, scv.z, cnt * shv.z);
        vv4[3] = fmaf(av.w, scv.w, cnt * shv.w);
#pragma unroll
        for (int u = 0; u < 4; u++) {
            unsigned long long vv = pack2f(vv4[u], vv4[u]);
            const ulonglong2* wr = reinterpret_cast<const ulonglong2*>(&swa[(k4 * 4 + u) * 64]);
#pragma unroll
            for (int j = 0; j < 16; j++) {
                ulonglong2 w = wr[j];
                fma2(acc[2 * j], vv, w.x);
                fma2(acc[2 * j + 1], vv, w.y);
            }
        }
    }
    float t[64];
#pragma unroll
    for (int j = 0; j < 32; j++) {
        float lo, hi; unpack2f(acc[j], lo, hi);
        t[2 * j] = fmaxf(lo, 0.f); t[2 * j + 1] = fmaxf(hi, 0.f);
    }

    float* prow = nullptr;
    float* orow = nullptr;
    if (L == 3) {
        int b = batch[n];
        prow = g_pool + (size_t)b * HID;
    } else {
        orow = g_h2 + (size_t)n * HID;
    }

    // ---- GEMM 2: chunks of 16 outputs (8 packed accumulators) ----
    const unsigned long long* sbb2 = reinterpret_cast<const unsigned long long*>(sbb);
#pragma unroll
    for (int j0 = 0; j0 < 64; j0 += 16) {
        unsigned long long o[8];
#pragma unroll
        for (int u = 0; u < 8; u++) o[u] = sbb2[j0 / 2 + u];
#pragma unroll 8
        for (int k = 0; k < 64; k++) {
            unsigned long long vv = pack2f(t[k], t[k]);
            const ulonglong2* wr = reinterpret_cast<const ulonglong2*>(&swb[k * 64 + j0]);
#pragma unroll
            for (int j = 0; j < 4; j++) {
                ulonglong2 w = wr[j];
                fma2(o[2 * j], vv, w.x);
                fma2(o[2 * j + 1], vv, w.y);
            }
        }
        float r[16];
#pragma unroll
        for (int u = 0; u < 8; u++) {
            float lo, hi; unpack2f(o[u], lo, hi);
            r[2 * u] = fmaxf(lo, 0.f); r[2 * u + 1] = fmaxf(hi, 0.f);
        }
        if (L == 3) {
#pragma unroll
            for (int j = 0; j < 16; j += 4)
                red_add_v4(prow + j0 + j, make_float4(r[j], r[j + 1], r[j + 2], r[j + 3]));
        } else {
#pragma unroll
            for (int j = 0; j < 16; j += 4)
                *reinterpret_cast<float4*>(orow + j0 + j) =
                    make_float4(r[j], r[j + 1], r[j + 2], r[j + 3]);
        }
    }
}

// ---------------- per-channel sum / sumsq over all nodes ----------------
template <int L>
__global__ __launch_bounds__(256) void stats64() {
    const float* __restrict__ h = (L == 1) ? g_h1 : g_h2;
    float* __restrict__ st      = (L == 1) ? g_stats1 : g_stats2;

    __shared__ float rs[64], rq[64];
    if (threadIdx.x < 64) { rs[threadIdx.x] = 0.f; rq[threadIdx.x] = 0.f; }
    __syncthreads();

    int tid = blockIdx.x * 256 + threadIdx.x;
    int cg = tid & 15;
    const int stride = (gridDim.x * 256) >> 4;
    float4 s = make_float4(0.f, 0.f, 0.f, 0.f);
    float4 q = make_float4(0.f, 0.f, 0.f, 0.f);
    for (int n = tid >> 4; n < N_NODES; n += stride) {
        float4 v = *reinterpret_cast<const float4*>(h + (size_t)n * HID + cg * 4);
        s.x += v.x; s.y += v.y; s.z += v.z; s.w += v.w;
        q.x = fmaf(v.x, v.x, q.x); q.y = fmaf(v.y, v.y, q.y);
        q.z = fmaf(v.z, v.z, q.z); q.w = fmaf(v.w, v.w, q.w);
    }
    atomicAdd(&rs[cg * 4 + 0], s.x); atomicAdd(&rs[cg * 4 + 1], s.y);
    atomicAdd(&rs[cg * 4 + 2], s.z); atomicAdd(&rs[cg * 4 + 3], s.w);
    atomicAdd(&rq[cg * 4 + 0], q.x); atomicAdd(&rq[cg * 4 + 1], q.y);
    atomicAdd(&rq[cg * 4 + 2], q.z); atomicAdd(&rq[cg * 4 + 3], q.w);
    __syncthreads();
    if (threadIdx.x < 64) {
        atomicAdd(&st[threadIdx.x], rs[threadIdx.x]);
        atomicAdd(&st[64 + threadIdx.x], rq[threadIdx.x]);
    }
}

// ---------------- stats -> BN scale/shift ----------------
template <int L>
__global__ void mkscale(const float* __restrict__ gma, const float* __restrict__ bet) {
    const float* __restrict__ st = (L == 1) ? g_stats1 : g_stats2;
    float* __restrict__ sc       = (L == 1) ? g_sc1 : g_sc2;
    float* __restrict__ sh       = (L == 1) ? g_sh1 : g_sh2;
    int j = threadIdx.x;
    float mean = st[j] * (1.0f / N_NODES);
    float var  = st[64 + j] * (1.0f / N_NODES) - mean * mean;
    float inv  = rsqrtf(var + 1e-5f);
    float s    = gma[j] * inv;
    sc[j] = s;
    sh[j] = fmaf(-mean, s, bet[j]);
}

// ---------------- head ----------------
__global__ __launch_bounds__(256) void final_head(
    const int* __restrict__ batch,
    const float* __restrict__ g3, const float* __restrict__ be3,
    const float* __restrict__ w1, const float* __restrict__ b1,
    const float* __restrict__ w2, const float* __restrict__ b2,
    float* __restrict__ out)
{
    __shared__ float ssc[64], ssh[64], sw1[64 * 32], sb1[32], sw2[32 * 10], sb2[10];
    __shared__ float scount[N_GRAPHS];
    int t = threadIdx.x;
    for (int i = t; i < 2048; i += 256) sw1[i] = w1[i];
    for (int i = t; i < 320; i += 256) sw2[i] = w2[i];
    if (t < 32) sb1[t] = b1[t];
    if (t < 10) sb2[t] = b2[t];

    {
        int lo = 0, hi = N_NODES;
        while (lo < hi) { int m = (lo + hi) >> 1; if (batch[m] < t) lo = m + 1; else hi = m; }
        int start = lo;
        lo = start; hi = N_NODES;
        while (lo < hi) { int m = (lo + hi) >> 1; if (batch[m] <= t) lo = m + 1; else hi = m; }
        scount[t] = fmaxf((float)(lo - start), 1.0f);
    }
    __syncthreads();

    if (t < 64) {
        float s = 0.f, q = 0.f;
        for (int gi = 0; gi < N_GRAPHS; gi++) {
            float v = g_pool[gi * HID + t] / scount[gi];
            s += v;
            q = fmaf(v, v, q);
        }
        float mean = s * (1.0f / N_GRAPHS);
        float var  = q * (1.0f / N_GRAPHS) - mean * mean;
        float inv  = rsqrtf(var + 1e-5f);
        float sg   = g3[t] * inv;
        ssc[t] = sg;
        ssh[t] = fmaf(-mean, sg, be3[t]);
    }
    __syncthreads();

    float invc = 1.0f / scount[t];
    float xb[64];
#pragma unroll
    for (int j = 0; j < 64; j++)
        xb[j] = fmaf(g_pool[t * HID + j] * invc, ssc[j], ssh[j]);

    float p[32];
#pragma unroll
    for (int j = 0; j < 32; j++) p[j] = sb1[j];
#pragma unroll 8
    for (int k = 0; k < 64; k++) {
        float v = xb[k];
#pragma unroll
        for (int j = 0; j < 32; j++) p[j] = fmaf(v, sw1[k * 32 + j], p[j]);
    }
#pragma unroll
    for (int j = 0; j < 32; j++) p[j] = (p[j] > 0.0f) ? p[j] : expm1f(p[j]);

    float o[10];
#pragma unroll
    for (int j = 0; j < 10; j++) o[j] = sb2[j];
#pragma unroll
    for (int k = 0; k < 32; k++) {
        float v = p[k];
#pragma unroll
        for (int j = 0; j < 10; j++) o[j] = fmaf(v, sw2[k * 10 + j], o[j]);
    }
    float m = o[0];
#pragma unroll
    for (int j = 1; j < 10; j++) m = fmaxf(m, o[j]);
    float se = 0.f;
#pragma unroll
    for (int j = 0; j < 10; j++) se += expf(o[j] - m);
    float lse = logf(se);
#pragma unroll
    for (int j = 0; j < 10; j++) out[t * 10 + j] = o[j] - m - lse;
}

// ---------------- launch (two-stream fork/join, capture-safe) --------------
extern "C" void kernel_launch(void* const* d_in, const int* in_sizes, int n_in,
                              void* d_out, int out_size)
{
    const float* x     = (const float*)d_in[0];
    const int*   ei    = (const int*)d_in[1];
    const int*   batch = (const int*)d_in[2];
    const float* w1a = (const float*)d_in[3];
    const float* b1a = (const float*)d_in[4];
    const float* w1b = (const float*)d_in[5];
    const float* b1b = (const float*)d_in[6];
    const float* eps1 = (const float*)d_in[7];
    const float* g1  = (const float*)d_in[8];
    const float* be1 = (const float*)d_in[9];
    const float* w2a = (const float*)d_in[10];
    const float* b2a = (const float*)d_in[11];
    const float* w2b = (const float*)d_in[12];
    const float* b2b = (const float*)d_in[13];
    const float* eps2 = (const float*)d_in[14];
    const float* g2  = (const float*)d_in[15];
    const float* be2 = (const float*)d_in[16];
    const float* w3a = (const float*)d_in[17];
    const float* b3a = (const float*)d_in[18];
    const float* w3b = (const float*)d_in[19];
    const float* b3b = (const float*)d_in[20];
    const float* eps3 = (const float*)d_in[21];
    const float* g3  = (const float*)d_in[22];
    const float* be3 = (const float*)d_in[23];
    const float* fc1w = (const float*)d_in[24];
    const float* fc1b = (const float*)d_in[25];
    const float* fc2w = (const float*)d_in[26];
    const float* fc2b = (const float*)d_in[27];
    float* out = (float*)d_out;

    const int nodeBlocks = (N_NODES + 127) / 128;
    const int edgeBlocks = (N_EDGES + 255) / 256;
    const int aggBlocks  = (N_NODES * 32 + 255) / 256;   // warp per node

    // one-time host-side infra (stream + events); device work identical every call
    static bool s_init = false;
    static cudaStream_t s2;
    static cudaEvent_t evE, evBuild, evH1, evS1, evH2, evS2;
    if (!s_init) {
        cudaStreamCreateWithFlags(&s2, cudaStreamNonBlocking);
        cudaEventCreateWithFlags(&evE,     cudaEventDisableTiming);
        cudaEventCreateWithFlags(&evBuild, cudaEventDisableTiming);
        cudaEventCreateWithFlags(&evH1,    cudaEventDisableTiming);
        cudaEventCreateWithFlags(&evS1,    cudaEventDisableTiming);
        cudaEventCreateWithFlags(&evH2,    cudaEventDisableTiming);
        cudaEventCreateWithFlags(&evS2,    cudaEventDisableTiming);
        s_init = true;
    }

    // s0: zero, merged edge pass (deg hist + 3-ch scatter)
    zero_small<<<SCAN_NB, 256>>>();
    k_edge1<<<edgeBlocks, 256>>>(ei, x);
    cudaEventRecord(evE, 0);

    // s2: CSR build chain (needs deg from merged pass)
    cudaStreamWaitEvent(s2, evE, 0);
    k_scanA<<<SCAN_NB, 256, 0, s2>>>();
    k_scanB<<<1, 512, 0, s2>>>();
    k_scanC<<<SCAN_NB, 256, 0, s2>>>();
    k_build<<<edgeBlocks, 256, 0, s2>>>(ei);
    cudaEventRecord(evBuild, s2);

    // s0: layer 1 MLP (overlaps CSR build on s2)
    node_mlp1<<<nodeBlocks, 128>>>(x, eps1, w1a, b1a, w1b, b1b);
    cudaEventRecord(evH1, 0);

    // s2: stats/mkscale for layer 1 (overlaps agg64<2> on s0)
    cudaStreamWaitEvent(s2, evH1, 0);
    stats64<1><<<512, 256, 0, s2>>>();
    mkscale<1><<<1, 64, 0, s2>>>(g1, be1);
    cudaEventRecord(evS1, s2);

    // s0: raw aggregate for layer 2 (needs h1 + CSR, not BN scales)
    cudaStreamWaitEvent(0, evBuild, 0);
    k_agg64<2><<<aggBlocks, 256>>>(eps2);
    cudaStreamWaitEvent(0, evS1, 0);
    node_mlp64<2><<<nodeBlocks, 128>>>(eps2, w2a, b2a, w2b, b2b, batch);
    cudaEventRecord(evH2, 0);

    // s2: stats/mkscale for layer 2 (overlaps agg64<3> on s0)
    cudaStreamWaitEvent(s2, evH2, 0);
    stats64<2><<<512, 256, 0, s2>>>();
    mkscale<2><<<1, 64, 0, s2>>>(g2, be2);
    cudaEventRecord(evS2, s2);

    // s0: raw aggregate for layer 3, then MLP (+pool) and head
    k_agg64<3><<<aggBlocks, 256>>>(eps3);
    cudaStreamWaitEvent(0, evS2, 0);
    node_mlp64<3><<<nodeBlocks, 128>>>(eps3, w3a, b3a, w3b, b3b, batch);
    final_head<<<1, 256>>>(batch, g3, be3, fc1w, fc1b, fc2w, fc2b, out);
}

// round 17
// speedup vs baseline: 1.0490x; 1.0490x over previous
#include <cuda_runtime.h>
#include <math.h>

#define N_NODES  100000
#define N_EDGES  1200000
#define N_GRAPHS 256
#define HID      64
#define SCAN_NB  391   // ceil(N_NODES / 256)

// ---------------- scratch (device globals: allocation-free) ----------------
__device__ __align__(16) float g_h1[N_NODES * HID];
__device__ __align__(16) float g_h2[N_NODES * HID];
__device__ __align__(16) float g_agg1[N_NODES * 3];
__device__ __align__(16) float g_agg2[N_NODES * HID];
__device__ __align__(16) float g_agg3[N_NODES * HID];
__device__ float g_stats1[128];
__device__ float g_stats2[128];
__device__ float g_sc1[64], g_sh1[64];
__device__ float g_sc2[64], g_sh2[64];
__device__ __align__(16) float g_pool[N_GRAPHS * HID];
// CSR-by-destination
__device__ int g_deg[N_NODES];
__device__ int g_off[N_NODES + 1];
__device__ int g_cur[N_NODES];
__device__ int g_csr[N_EDGES];
__device__ int g_bsums[512];

// ---------------- helpers ----------------
__device__ __forceinline__ void red_add_v4(float* p, float4 v) {
    asm volatile("red.global.add.v4.f32 [%0], {%1,%2,%3,%4};"
                 :: "l"(p), "f"(v.x), "f"(v.y), "f"(v.z), "f"(v.w)
                 : "memory");
}
// packed fp32x2 FMA (Blackwell): d = a * b + d, on two fp32 lanes at once
__device__ __forceinline__ unsigned long long pack2f(float lo, float hi) {
    unsigned long long r;
    asm("mov.b64 %0, {%1, %2};" : "=l"(r) : "f"(lo), "f"(hi));
    return r;
}
__device__ __forceinline__ void unpack2f(unsigned long long v, float& lo, float& hi) {
    asm("mov.b64 {%0, %1}, %2;" : "=f"(lo), "=f"(hi) : "l"(v));
}
__device__ __forceinline__ void fma2(unsigned long long& d,
                                     unsigned long long a, unsigned long long b) {
    asm("fma.rn.f32x2 %0, %1, %2, %3;" : "=l"(d) : "l"(a), "l"(b), "l"(d));
}

// ---------------- zero small scratch (incl. agg1 for atomic scatter) -------
__global__ void zero_small() {
    int i = blockIdx.x * blockDim.x + threadIdx.x;
    if (i < N_NODES) {
        g_deg[i] = 0;
        g_agg1[i * 3 + 0] = 0.f;
        g_agg1[i * 3 + 1] = 0.f;
        g_agg1[i * 3 + 2] = 0.f;
    }
    if (i < 128) { g_stats1[i] = 0.f; g_stats2[i] = 0.f; }
    if (i < N_GRAPHS * 16)
        reinterpret_cast<float4*>(g_pool)[i] = make_float4(0.f, 0.f, 0.f, 0.f);
}

// ---------------- CSR build: hist -> scan -> scatter ----------------
__global__ void k_hist(const int* __restrict__ ei) {
    int e = blockIdx.x * blockDim.x + threadIdx.x;
    if (e < N_EDGES) atomicAdd(&g_deg[ei[N_EDGES + e]], 1);
}

__global__ void k_scanA() {
    __shared__ int sh[256];
    int t = threadIdx.x;
    int i = blockIdx.x * 256 + t;
    sh[t] = (i < N_NODES) ? g_deg[i] : 0;
    __syncthreads();
    for (int s = 128; s > 0; s >>= 1) {
        if (t < s) sh[t] += sh[t + s];
        __syncthreads();
    }
    if (t == 0) g_bsums[blockIdx.x] = sh[0];
}

__global__ void k_scanB() {
    __shared__ int a[512], b[512];
    int t = threadIdx.x;
    int v = (t < SCAN_NB) ? g_bsums[t] : 0;
    a[t] = v;
    __syncthreads();
    int* src = a; int* dst = b;
    for (int off = 1; off < 512; off <<= 1) {
        dst[t] = src[t] + ((t >= off) ? src[t - off] : 0);
        __syncthreads();
        int* tmp = src; src = dst; dst = tmp;
    }
    if (t < SCAN_NB) g_bsums[t] = src[t] - v;   // exclusive
}

__global__ void k_scanC() {
    __shared__ int a[256], b[256];
    int t = threadIdx.x;
    int i = blockIdx.x * 256 + t;
    int v = (i < N_NODES) ? g_deg[i] : 0;
    a[t] = v;
    __syncthreads();
    int* src = a; int* dst = b;
    for (int off = 1; off < 256; off <<= 1) {
        dst[t] = src[t] + ((t >= off) ? src[t - off] : 0);
        __syncthreads();
        int* tmp = src; src = dst; dst = tmp;
    }
    int excl = src[t] - v + g_bsums[blockIdx.x];
    if (i < N_NODES) { g_off[i] = excl; g_cur[i] = excl; }
    if (i == 0) g_off[N_NODES] = N_EDGES;
}

__global__ void k_build(const int* __restrict__ ei) {
    int e = blockIdx.x * blockDim.x + threadIdx.x;
    if (e >= N_EDGES) return;
    int d = ei[N_EDGES + e];
    int s = ei[e];
    int p = atomicAdd(&g_cur[d], 1);
    g_csr[p] = s;
}

// ---------------- layer-1 aggregate (3-ch atomic scatter, CSR-free) --------
__global__ void edge_scatter3(const int* __restrict__ ei, const float* __restrict__ x) {
    int e = blockIdx.x * blockDim.x + threadIdx.x;
    if (e >= N_EDGES) return;
    int s = ei[e];
    int d = ei[N_EDGES + e];
    const float* xr = x + 3 * (size_t)s;
    float* ar = g_agg1 + 3 * (size_t)d;
    atomicAdd(ar + 0, xr[0]);
    atomicAdd(ar + 1, xr[1]);
    atomicAdd(ar + 2, xr[2]);
}

// ---------------- 64-ch aggregate: RAW sums (BN applied later in MLP) ------
// out[n] = e1·h_n + Σ_{s→n} h_s        (warp-per-node, divergence-free)
template <int L>
__global__ __launch_bounds__(256) void k_agg64(const float* __restrict__ epsp) {
    const float* __restrict__ h = (L == 2) ? g_h1  : g_h2;
    float* __restrict__ agg     = (L == 2) ? g_agg2 : g_agg3;

    int n = (blockIdx.x * 256 + threadIdx.x) >> 5;   // one warp per node
    if (n >= N_NODES) return;
    int lane = threadIdx.x & 31;
    int c = lane * 2;
    int st = g_off[n], en = g_off[n + 1];
    float e1 = 1.0f + *epsp;

    float2 a = *reinterpret_cast<const float2*>(h + (size_t)n * HID + c);
    a.x *= e1; a.y *= e1;
    for (int e = st; e < en; e++) {
        int s = __ldg(&g_csr[e]);
        float2 v = *reinterpret_cast<const float2*>(h + (size_t)s * HID + c);
        a.x += v.x; a.y += v.y;
    }
    *reinterpret_cast<float2*>(agg + (size_t)n * HID + c) = a;
}

// ---------------- layer-1 node MLP: 3 -> 64 -> 64, outer relu ----------------
__global__ __launch_bounds__(128) void node_mlp1(
    const float* __restrict__ x, const float* __restrict__ epsp,
    const float* __restrict__ wa, const float* __restrict__ ba,
    const float* __restrict__ wb, const float* __restrict__ bb)
{
    __shared__ __align__(16) float swa[3 * 64];
    __shared__ __align__(16) float swb[64 * 64];
    __shared__ __align__(16) float sba[64];
    __shared__ __align__(16) float sbb[64];
    for (int i = threadIdx.x; i < 64 * 64; i += 128) swb[i] = wb[i];
    for (int i = threadIdx.x; i < 192; i += 128) swa[i] = wa[i];
    if (threadIdx.x < 64) { sba[threadIdx.x] = ba[threadIdx.x]; sbb[threadIdx.x] = bb[threadIdx.x]; }
    __syncthreads();

    int n = blockIdx.x * 128 + threadIdx.x;
    if (n >= N_NODES) return;
    float e1 = 1.0f + *epsp;
    float v0 = fmaf(e1, x[n * 3 + 0], g_agg1[n * 3 + 0]);
    float v1 = fmaf(e1, x[n * 3 + 1], g_agg1[n * 3 + 1]);
    float v2 = fmaf(e1, x[n * 3 + 2], g_agg1[n * 3 + 2]);

    float t[64];
#pragma unroll
    for (int j = 0; j < 64; j++)
        t[j] = fmaxf(fmaf(v2, swa[128 + j], fmaf(v1, swa[64 + j], fmaf(v0, swa[j], sba[j]))), 0.0f);

    // second GEMM with packed f32x2 FMA, chunks of 16 outputs
    float* orow = g_h1 + (size_t)n * HID;
    const unsigned long long* sbb2 = reinterpret_cast<const unsigned long long*>(sbb);
#pragma unroll
    for (int j0 = 0; j0 < 64; j0 += 16) {
        unsigned long long o[8];
#pragma unroll
        for (int u = 0; u < 8; u++) o[u] = sbb2[j0 / 2 + u];
#pragma unroll 8
        for (int k = 0; k < 64; k++) {
            unsigned long long vv = pack2f(t[k], t[k]);
            const ulonglong2* wr = reinterpret_cast<const ulonglong2*>(&swb[k * 64 + j0]);
#pragma unroll
            for (int j = 0; j < 4; j++) {
                ulonglong2 w = wr[j];
                fma2(o[2 * j], vv, w.x);
                fma2(o[2 * j + 1], vv, w.y);
            }
        }
        float r[16];
#pragma unroll
        for (int u = 0; u < 8; u++) {
            float lo, hi; unpack2f(o[u], lo, hi);
            r[2 * u] = fmaxf(lo, 0.f); r[2 * u + 1] = fmaxf(hi, 0.f);
        }
#pragma unroll
        for (int j = 0; j < 16; j += 4)
            *reinterpret_cast<float4*>(orow + j0 + j) =
                make_float4(r[j], r[j + 1], r[j + 2], r[j + 3]);
    }
}

// ---------------- layer-2/3 node MLP: BN-fold at input + 64->64->64 --------
// v = sc ⊙ a_raw + (e1 + deg)·sh ; packed f32x2 FMA throughout
template <int L>
__global__ __launch_bounds__(128) void node_mlp64(
    const float* __restrict__ epsp,
    const float* __restrict__ wa, const float* __restrict__ ba,
    const float* __restrict__ wb, const float* __restrict__ bb,
    const int* __restrict__ batch)
{
    const float* __restrict__ agg = (L == 2) ? g_agg2 : g_agg3;
    const float* __restrict__ sc  = (L == 2) ? g_sc1 : g_sc2;
    const float* __restrict__ sh  = (L == 2) ? g_sh1 : g_sh2;

    __shared__ __align__(16) float swa[4096];
    __shared__ __align__(16) float swb[4096];
    __shared__ __align__(16) float sba[64];
    __shared__ __align__(16) float sbb[64];
    __shared__ __align__(16) float ssc[64];
    __shared__ __align__(16) float ssh[64];
    for (int i = threadIdx.x; i < 4096; i += 128) { swa[i] = wa[i]; swb[i] = wb[i]; }
    if (threadIdx.x < 64) {
        int j = threadIdx.x;
        sba[j] = ba[j]; sbb[j] = bb[j]; ssc[j] = sc[j]; ssh[j] = sh[j];
    }
    __syncthreads();

    int n = blockIdx.x * 128 + threadIdx.x;
    if (n >= N_NODES) return;
    float e1 = 1.0f + *epsp;
    float cnt = e1 + (float)(g_off[n + 1] - g_off[n]);
    const float4* ar4 = reinterpret_cast<const float4*>(agg + (size_t)n * HID);

    // ---- GEMM 1: all 64 outputs as 32 packed accumulators ----
    unsigned long long acc[32];
    const unsigned long long* sba2 = reinterpret_cast<const unsigned long long*>(sba);
#pragma unroll
    for (int j = 0; j < 32; j++) acc[j] = sba2[j];
#pragma unroll 4
    for (int k4 = 0; k4 < 16; k4++) {
        float4 av = ar4[k4];
        float4 scv = *reinterpret_cast<const float4*>(&ssc[k4 * 4]);
        float4 shv = *reinterpret_cast<const float4*>(&ssh[k4 * 4]);
        float vv4[4];
        vv4[0] = fmaf(av.x, scv.x, cnt * shv.x);
        vv4[1] = fmaf(av.y, scv.y, cnt * shv.y);
        vv4[2] = fmaf(av.z, scv.z, cnt * shv.z);
        vv4[3] = fmaf(av.w, scv.w, cnt * shv.w);
#pragma unroll
        for (int u = 0; u < 4; u++) {
            unsigned long long vv = pack2f(vv4[u], vv4[u]);
            const ulonglong2* wr = reinterpret_cast<const ulonglong2*>(&swa[(k4 * 4 + u) * 64]);
#pragma unroll
            for (int j = 0; j < 16; j++) {
                ulonglong2 w = wr[j];
                fma2(acc[2 * j], vv, w.x);
                fma2(acc[2 * j + 1], vv, w.y);
            }
        }
    }
    float t[64];
#pragma unroll
    for (int j = 0; j < 32; j++) {
        float lo, hi; unpack2f(acc[j], lo, hi);
        t[2 * j] = fmaxf(lo, 0.f); t[2 * j + 1] = fmaxf(hi, 0.f);
    }

    float* prow = nullptr;
    float* orow = nullptr;
    if (L == 3) {
        int b = batch[n];
        prow = g_pool + (size_t)b * HID;
    } else {
        orow = g_h2 + (size_t)n * HID;
    }

    // ---- GEMM 2: chunks of 16 outputs (8 packed accumulators) ----
    const unsigned long long* sbb2 = reinterpret_cast<const unsigned long long*>(sbb);
#pragma unroll
    for (int j0 = 0; j0 < 64; j0 += 16) {
        unsigned long long o[8];
#pragma unroll
        for (int u = 0; u < 8; u++) o[u] = sbb2[j0 / 2 + u];
#pragma unroll 8
        for (int k = 0; k < 64; k++) {
            unsigned long long vv = pack2f(t[k], t[k]);
            const ulonglong2* wr = reinterpret_cast<const ulonglong2*>(&swb[k * 64 + j0]);
#pragma unroll
            for (int j = 0; j < 4; j++) {
                ulonglong2 w = wr[j];
                fma2(o[2 * j], vv, w.x);
                fma2(o[2 * j + 1], vv, w.y);
            }
        }
        float r[16];
#pragma unroll
        for (int u = 0; u < 8; u++) {
            float lo, hi; unpack2f(o[u], lo, hi);
            r[2 * u] = fmaxf(lo, 0.f); r[2 * u + 1] = fmaxf(hi, 0.f);
        }
        if (L == 3) {
#pragma unroll
            for (int j = 0; j < 16; j += 4)
                red_add_v4(prow + j0 + j, make_float4(r[j], r[j + 1], r[j + 2], r[j + 3]));
        } else {
#pragma unroll
            for (int j = 0; j < 16; j += 4)
                *reinterpret_cast<float4*>(orow + j0 + j) =
                    make_float4(r[j], r[j + 1], r[j + 2], r[j + 3]);
        }
    }
}

// ---------------- per-channel sum / sumsq over all nodes ----------------
template <int L>
__global__ __launch_bounds__(256) void stats64() {
    const float* __restrict__ h = (L == 1) ? g_h1 : g_h2;
    float* __restrict__ st      = (L == 1) ? g_stats1 : g_stats2;

    __shared__ float rs[64], rq[64];
    if (threadIdx.x < 64) { rs[threadIdx.x] = 0.f; rq[threadIdx.x] = 0.f; }
    __syncthreads();

    int tid = blockIdx.x * 256 + threadIdx.x;
    int cg = tid & 15;
    const int stride = (gridDim.x * 256) >> 4;
    float4 s = make_float4(0.f, 0.f, 0.f, 0.f);
    float4 q = make_float4(0.f, 0.f, 0.f, 0.f);
    for (int n = tid >> 4; n < N_NODES; n += stride) {
        float4 v = *reinterpret_cast<const float4*>(h + (size_t)n * HID + cg * 4);
        s.x += v.x; s.y += v.y; s.z += v.z; s.w += v.w;
        q.x = fmaf(v.x, v.x, q.x); q.y = fmaf(v.y, v.y, q.y);
        q.z = fmaf(v.z, v.z, q.z); q.w = fmaf(v.w, v.w, q.w);
    }
    atomicAdd(&rs[cg * 4 + 0], s.x); atomicAdd(&rs[cg * 4 + 1], s.y);
    atomicAdd(&rs[cg * 4 + 2], s.z); atomicAdd(&rs[cg * 4 + 3], s.w);
    atomicAdd(&rq[cg * 4 + 0], q.x); atomicAdd(&rq[cg * 4 + 1], q.y);
    atomicAdd(&rq[cg * 4 + 2], q.z); atomicAdd(&rq[cg * 4 + 3], q.w);
    __syncthreads();
    if (threadIdx.x < 64) {
        atomicAdd(&st[threadIdx.x], rs[threadIdx.x]);
        atomicAdd(&st[64 + threadIdx.x], rq[threadIdx.x]);
    }
}

// ---------------- stats -> BN scale/shift ----------------
template <int L>
__global__ void mkscale(const float* __restrict__ gma, const float* __restrict__ bet) {
    const float* __restrict__ st = (L == 1) ? g_stats1 : g_stats2;
    float* __restrict__ sc       = (L == 1) ? g_sc1 : g_sc2;
    float* __restrict__ sh       = (L == 1) ? g_sh1 : g_sh2;
    int j = threadIdx.x;
    float mean = st[j] * (1.0f / N_NODES);
    float var  = st[64 + j] * (1.0f / N_NODES) - mean * mean;
    float inv  = rsqrtf(var + 1e-5f);
    float s    = gma[j] * inv;
    sc[j] = s;
    sh[j] = fmaf(-mean, s, bet[j]);
}

// ---------------- head ----------------
__global__ __launch_bounds__(256) void final_head(
    const int* __restrict__ batch,
    const float* __restrict__ g3, const float* __restrict__ be3,
    const float* __restrict__ w1, const float* __restrict__ b1,
    const float* __restrict__ w2, const float* __restrict__ b2,
    float* __restrict__ out)
{
    __shared__ float ssc[64], ssh[64], sw1[64 * 32], sb1[32], sw2[32 * 10], sb2[10];
    __shared__ float scount[N_GRAPHS];
    int t = threadIdx.x;
    for (int i = t; i < 2048; i += 256) sw1[i] = w1[i];
    for (int i = t; i < 320; i += 256) sw2[i] = w2[i];
    if (t < 32) sb1[t] = b1[t];
    if (t < 10) sb2[t] = b2[t];

    {
        int lo = 0, hi = N_NODES;
        while (lo < hi) { int m = (lo + hi) >> 1; if (batch[m] < t) lo = m + 1; else hi = m; }
        int start = lo;
        lo = start; hi = N_NODES;
        while (lo < hi) { int m = (lo + hi) >> 1; if (batch[m] <= t) lo = m + 1; else hi = m; }
        scount[t] = fmaxf((float)(lo - start), 1.0f);
    }
    __syncthreads();

    if (t < 64) {
        float s = 0.f, q = 0.f;
        for (int gi = 0; gi < N_GRAPHS; gi++) {
            float v = g_pool[gi * HID + t] / scount[gi];
            s += v;
            q = fmaf(v, v, q);
        }
        float mean = s * (1.0f / N_GRAPHS);
        float var  = q * (1.0f / N_GRAPHS) - mean * mean;
        float inv  = rsqrtf(var + 1e-5f);
        float sg   = g3[t] * inv;
        ssc[t] = sg;
        ssh[t] = fmaf(-mean, sg, be3[t]);
    }
    __syncthreads();

    float invc = 1.0f / scount[t];
    float xb[64];
#pragma unroll
    for (int j = 0; j < 64; j++)
        xb[j] = fmaf(g_pool[t * HID + j] * invc, ssc[j], ssh[j]);

    float p[32];
#pragma unroll
    for (int j = 0; j < 32; j++) p[j] = sb1[j];
#pragma unroll 8
    for (int k = 0; k < 64; k++) {
        float v = xb[k];
#pragma unroll
        for (int j = 0; j < 32; j++) p[j] = fmaf(v, sw1[k * 32 + j], p[j]);
    }
#pragma unroll
    for (int j = 0; j < 32; j++) p[j] = (p[j] > 0.0f) ? p[j] : expm1f(p[j]);

    float o[10];
#pragma unroll
    for (int j = 0; j < 10; j++) o[j] = sb2[j];
#pragma unroll
    for (int k = 0; k < 32; k++) {
        float v = p[k];
#pragma unroll
        for (int j = 0; j < 10; j++) o[j] = fmaf(v, sw2[k * 10 + j], o[j]);
    }
    float m = o[0];
#pragma unroll
    for (int j = 1; j < 10; j++) m = fmaxf(m, o[j]);
    float se = 0.f;
#pragma unroll
    for (int j = 0; j < 10; j++) se += expf(o[j] - m);
    float lse = logf(se);
#pragma unroll
    for (int j = 0; j < 10; j++) out[t * 10 + j] = o[j] - m - lse;
}

// ---------------- launch (two-stream fork/join, capture-safe) --------------
extern "C" void kernel_launch(void* const* d_in, const int* in_sizes, int n_in,
                              void* d_out, int out_size)
{
    const float* x     = (const float*)d_in[0];
    const int*   ei    = (const int*)d_in[1];
    const int*   batch = (const int*)d_in[2];
    const float* w1a = (const float*)d_in[3];
    const float* b1a = (const float*)d_in[4];
    const float* w1b = (const float*)d_in[5];
    const float* b1b = (const float*)d_in[6];
    const float* eps1 = (const float*)d_in[7];
    const float* g1  = (const float*)d_in[8];
    const float* be1 = (const float*)d_in[9];
    const float* w2a = (const float*)d_in[10];
    const float* b2a = (const float*)d_in[11];
    const float* w2b = (const float*)d_in[12];
    const float* b2b = (const float*)d_in[13];
    const float* eps2 = (const float*)d_in[14];
    const float* g2  = (const float*)d_in[15];
    const float* be2 = (const float*)d_in[16];
    const float* w3a = (const float*)d_in[17];
    const float* b3a = (const float*)d_in[18];
    const float* w3b = (const float*)d_in[19];
    const float* b3b = (const float*)d_in[20];
    const float* eps3 = (const float*)d_in[21];
    const float* g3  = (const float*)d_in[22];
    const float* be3 = (const float*)d_in[23];
    const float* fc1w = (const float*)d_in[24];
    const float* fc1b = (const float*)d_in[25];
    const float* fc2w = (const float*)d_in[26];
    const float* fc2b = (const float*)d_in[27];
    float* out = (float*)d_out;

    const int nodeBlocks = (N_NODES + 127) / 128;
    const int edgeBlocks = (N_EDGES + 255) / 256;
    const int aggBlocks  = (N_NODES * 32 + 255) / 256;   // warp per node

    // one-time host-side infra (stream + events); device work identical every call
    static bool s_init = false;
    static cudaStream_t s2;
    static cudaEvent_t evFork, evBuild, evH1, evS1, evH2, evS2;
    if (!s_init) {
        cudaStreamCreateWithFlags(&s2, cudaStreamNonBlocking);
        cudaEventCreateWithFlags(&evFork,  cudaEventDisableTiming);
        cudaEventCreateWithFlags(&evBuild, cudaEventDisableTiming);
        cudaEventCreateWithFlags(&evH1,    cudaEventDisableTiming);
        cudaEventCreateWithFlags(&evS1,    cudaEventDisableTiming);
        cudaEventCreateWithFlags(&evH2,    cudaEventDisableTiming);
        cudaEventCreateWithFlags(&evS2,    cudaEventDisableTiming);
        s_init = true;
    }

    // s0: zero, then fork
    zero_small<<<SCAN_NB, 256>>>();
    cudaEventRecord(evFork, 0);
    cudaStreamWaitEvent(s2, evFork, 0);

    // s2: CSR build chain (independent of layer-1 compute)
    k_hist<<<edgeBlocks, 256, 0, s2>>>(ei);
    k_scanA<<<SCAN_NB, 256, 0, s2>>>();
    k_scanB<<<1, 512, 0, s2>>>();
    k_scanC<<<SCAN_NB, 256, 0, s2>>>();
    k_build<<<edgeBlocks, 256, 0, s2>>>(ei);
    cudaEventRecord(evBuild, s2);

    // s0: layer 1 (atomic 3-ch scatter needs no CSR)
    edge_scatter3<<<edgeBlocks, 256>>>(ei, x);
    node_mlp1<<<nodeBlocks, 128>>>(x, eps1, w1a, b1a, w1b, b1b);
    cudaEventRecord(evH1, 0);

    // s2: stats/mkscale for layer 1 (overlaps agg64<2> on s0)
    cudaStreamWaitEvent(s2, evH1, 0);
    stats64<1><<<512, 256, 0, s2>>>();
    mkscale<1><<<1, 64, 0, s2>>>(g1, be1);
    cudaEventRecord(evS1, s2);

    // s0: raw aggregate for layer 2 (needs h1 + CSR, NOT BN scales)
    cudaStreamWaitEvent(0, evBuild, 0);
    k_agg64<2><<<aggBlocks, 256>>>(eps2);
    cudaStreamWaitEvent(0, evS1, 0);
    node_mlp64<2><<<nodeBlocks, 128>>>(eps2, w2a, b2a, w2b, b2b, batch);
    cudaEventRecord(evH2, 0);

    // s2: stats/mkscale for layer 2 (overlaps agg64<3> on s0)
    cudaStreamWaitEvent(s2, evH2, 0);
    stats64<2><<<512, 256, 0, s2>>>();
    mkscale<2><<<1, 64, 0, s2>>>(g2, be2);
    cudaEventRecord(evS2, s2);

    // s0: raw aggregate for layer 3, then MLP (+pool) and head
    k_agg64<3><<<aggBlocks, 256>>>(eps3);
    cudaStreamWaitEvent(0, evS2, 0);
    node_mlp64<3><<<nodeBlocks, 128>>>(eps3, w3a, b3a, w3b, b3b, batch);
    final_head<<<1, 256>>>(batch, g3, be3, fc1w, fc1b, fc2w, fc2b, out);
}